// round 3
// baseline (speedup 1.0000x reference)
#include <cuda_runtime.h>
#include <cuda_fp16.h>
#include <mma.h>

using namespace nvcuda;

constexpr int E_   = 12;
constexpr int T_   = 2048;
constexpr int H_   = 64;
constexpr int IN_  = 128;
constexpr int K3H  = 192;
constexpr int ITERS = 10;
constexpr int KTOT = E_*H_ + H_;    // 832

// ---------------------------------------------------------------------------
// Device scratch (hi/lo fp16 split representations)
// ---------------------------------------------------------------------------
__device__ __half g_eh[(size_t)E_*T_*T_];   // edge hi  (~96 MB)
__device__ __half g_el[(size_t)E_*T_*T_];   // edge lo  (~96 MB)
__device__ __half g_hh[T_*H_], g_hl[T_*H_]; // hidden hi/lo
__device__ __half g_ah[(size_t)E_*T_*H_];   // act hi
__device__ __half g_al[(size_t)E_*T_*H_];   // act lo
__device__ __half g_Bh[KTOT*K3H], g_Bl[KTOT*K3H];
__device__ float  g_iw[T_*K3H];
__device__ float  g_awzrh[T_*K3H];
__device__ float  g_hbuf[2][T_*H_];

// ---------------------------------------------------------------------------
// Helpers
// ---------------------------------------------------------------------------
__device__ __forceinline__ void cp16(void* s, const void* g) {
    unsigned sa = (unsigned)__cvta_generic_to_shared(s);
    asm volatile("cp.async.ca.shared.global [%0], [%1], 16;\n" :: "r"(sa), "l"(g));
}
__device__ __forceinline__ void cp_commit() { asm volatile("cp.async.commit_group;\n"); }

// ---------------------------------------------------------------------------
// Pre-pass
// ---------------------------------------------------------------------------
__global__ void p1_conv_edge(const float* __restrict__ e) {
    size_t i = (size_t)blockIdx.x * blockDim.x + threadIdx.x;   // one float4 each
    float4 v = reinterpret_cast<const float4*>(e)[i];
    __half hx = __float2half_rn(v.x), hy = __float2half_rn(v.y);
    __half hz = __float2half_rn(v.z), hw = __float2half_rn(v.w);
    __half2* dh = reinterpret_cast<__half2*>(g_eh);
    __half2* dl = reinterpret_cast<__half2*>(g_el);
    dh[2*i]   = __halves2half2(hx, hy);
    dh[2*i+1] = __halves2half2(hz, hw);
    dl[2*i]   = __floats2half2_rn(v.x - __half2float(hx), v.y - __half2float(hy));
    dl[2*i+1] = __floats2half2_rn(v.z - __half2float(hz), v.w - __half2float(hw));
}

__global__ void p2_build_b(const float* __restrict__ w, const float* __restrict__ uzr) {
    int i = blockIdx.x * blockDim.x + threadIdx.x;
    if (i >= KTOT * K3H) return;
    int k = i / K3H, n = i % K3H;
    float v;
    if (k < E_*H_) v = w[i];
    else { int j = k - E_*H_; v = (n < 2*H_) ? uzr[j*2*H_ + n] : 0.0f; }
    __half hi = __float2half_rn(v);
    g_Bh[i] = hi;
    g_Bl[i] = __float2half_rn(v - __half2float(hi));
}

__global__ void p4_h16(const float* __restrict__ h) {
    int i = blockIdx.x * blockDim.x + threadIdx.x;
    float v = h[i];
    __half hi = __float2half_rn(v);
    g_hh[i] = hi;
    g_hl[i] = __float2half_rn(v - __half2float(hi));
}

__global__ void p3_iw(const float* __restrict__ x, const float* __restrict__ wi,
                      const float* __restrict__ bw) {
    __shared__ float xs[IN_];
    int t = blockIdx.x;
    if (threadIdx.x < IN_) xs[threadIdx.x] = x[t*IN_ + threadIdx.x];
    __syncthreads();
    int n = threadIdx.x;
    float acc = bw[n];
    #pragma unroll 8
    for (int k = 0; k < IN_; k++) acc += xs[k] * wi[k*K3H + n];
    g_iw[t*K3H + n] = acc;
}

// ---------------------------------------------------------------------------
// K1: act = edge^T @ h  in double-fp16 (3-term), + ba. Outputs act hi/lo.
// A(k=s, m=t) col-major tiles from edge planes; B(k=s, n=h) from h planes.
// 64x64 tile, 4 warps (2x2 of 32x32), cp.async double buffer.
// ---------------------------------------------------------------------------
constexpr int LDA = 72, LDB = 72, LDC = 68;
constexpr int STG = 64 * LDA;                   // halves per stage-array
constexpr int SMEM_K1 = 4 * 2 * STG * 2;        // bytes = 73728

__global__ __launch_bounds__(128) void k1_act(const float* __restrict__ ba) {
    extern __shared__ __half smem[];
    __half* Ah = smem;
    __half* Al = smem + 2*STG;
    __half* Bh = smem + 4*STG;
    __half* Bl = smem + 6*STG;

    const int e  = blockIdx.y;
    const int m0 = blockIdx.x * 64;
    const __half* Agh = g_eh + (size_t)e * T_ * T_;
    const __half* Agl = g_el + (size_t)e * T_ * T_;

    const int tid  = threadIdx.x;
    const int warp = tid >> 5;
    const int wm = (warp & 1) * 32, wn = (warp >> 1) * 32;
    const int lr = tid >> 3;          // 0..15
    const int lc = (tid & 7) * 8;     // halves, 16B aligned

    wmma::fragment<wmma::accumulator, 16,16,16, float> accM[2][2], accL[2][2];
    #pragma unroll
    for (int i = 0; i < 2; i++)
        #pragma unroll
        for (int j = 0; j < 2; j++) { wmma::fill_fragment(accM[i][j], 0.0f);
                                      wmma::fill_fragment(accL[i][j], 0.0f); }

    auto load_stage = [&](int st, int k0) {
        #pragma unroll
        for (int t = 0; t < 4; t++) {
            int r = lr + 16*t;
            cp16(&Ah[(st*64 + r)*LDA + lc], Agh + (size_t)(k0 + r)*T_ + m0 + lc);
            cp16(&Al[(st*64 + r)*LDA + lc], Agl + (size_t)(k0 + r)*T_ + m0 + lc);
            cp16(&Bh[(st*64 + r)*LDB + lc], g_hh + (k0 + r)*H_ + lc);
            cp16(&Bl[(st*64 + r)*LDB + lc], g_hl + (k0 + r)*H_ + lc);
        }
        cp_commit();
    };

    load_stage(0, 0);
    int st = 0;
    for (int kb = 0; kb < T_/64; kb++) {
        if (kb + 1 < T_/64) {
            load_stage(st ^ 1, (kb + 1) * 64);
            asm volatile("cp.async.wait_group 1;\n");
        } else {
            asm volatile("cp.async.wait_group 0;\n");
        }
        __syncthreads();

        const __half* As_ = &Ah[st*64*LDA];
        const __half* Al_ = &Al[st*64*LDA];
        const __half* Bs_ = &Bh[st*64*LDB];
        const __half* Bl_ = &Bl[st*64*LDB];
        #pragma unroll
        for (int kk = 0; kk < 64; kk += 16) {
            wmma::fragment<wmma::matrix_a, 16,16,16, __half, wmma::col_major> afh[2], afl[2];
            wmma::fragment<wmma::matrix_b, 16,16,16, __half, wmma::row_major> bfh[2], bfl[2];
            #pragma unroll
            for (int i = 0; i < 2; i++) {
                wmma::load_matrix_sync(afh[i], As_ + kk*LDA + wm + i*16, LDA);
                wmma::load_matrix_sync(afl[i], Al_ + kk*LDA + wm + i*16, LDA);
            }
            #pragma unroll
            for (int j = 0; j < 2; j++) {
                wmma::load_matrix_sync(bfh[j], Bs_ + kk*LDB + wn + j*16, LDB);
                wmma::load_matrix_sync(bfl[j], Bl_ + kk*LDB + wn + j*16, LDB);
            }
            #pragma unroll
            for (int i = 0; i < 2; i++)
                #pragma unroll
                for (int j = 0; j < 2; j++) {
                    wmma::mma_sync(accM[i][j], afh[i], bfh[j], accM[i][j]);
                    wmma::mma_sync(accM[i][j], afh[i], bfl[j], accM[i][j]);
                    wmma::mma_sync(accL[i][j], afl[i], bfh[j], accL[i][j]);
                }
        }
        __syncthreads();
        st ^= 1;
    }

    // combine + epilogue through smem (reuse stage memory)
    #pragma unroll
    for (int i = 0; i < 2; i++)
        #pragma unroll
        for (int j = 0; j < 2; j++)
            #pragma unroll
            for (int k = 0; k < accM[i][j].num_elements; k++)
                accM[i][j].x[k] += accL[i][j].x[k];

    float* Cs = reinterpret_cast<float*>(smem);
    #pragma unroll
    for (int i = 0; i < 2; i++)
        #pragma unroll
        for (int j = 0; j < 2; j++)
            wmma::store_matrix_sync(Cs + (wm + 16*i)*LDC + wn + 16*j, accM[i][j],
                                    LDC, wmma::mem_row_major);
    __syncthreads();
    for (int idx = tid; idx < 64*64; idx += 128) {
        int r = idx >> 6, c = idx & 63;
        float v = Cs[r*LDC + c] + ba[e*H_ + c];
        __half hi = __float2half_rn(v);
        size_t o = ((size_t)e*T_ + m0 + r)*H_ + c;
        g_ah[o] = hi;
        g_al[o] = __float2half_rn(v - __half2float(hi));
    }
}

// ---------------------------------------------------------------------------
// K2: awzrh = [act | h] @ [W ; uz_ur|0]  (M=2048, K=832, N=192), 3-term split.
// ---------------------------------------------------------------------------
__global__ __launch_bounds__(128) void k2_awzrh() {
    extern __shared__ __half smem[];
    __half* Ah = smem;
    __half* Al = smem + 2*STG;
    __half* Bh = smem + 4*STG;
    __half* Bl = smem + 6*STG;

    const int m0 = blockIdx.x * 64;
    const int n0 = blockIdx.y * 64;
    const int tid  = threadIdx.x;
    const int warp = tid >> 5;
    const int wm = (warp & 1) * 32, wn = (warp >> 1) * 32;
    const int lr = tid >> 3;
    const int lc = (tid & 7) * 8;

    wmma::fragment<wmma::accumulator, 16,16,16, float> accM[2][2], accL[2][2];
    #pragma unroll
    for (int i = 0; i < 2; i++)
        #pragma unroll
        for (int j = 0; j < 2; j++) { wmma::fill_fragment(accM[i][j], 0.0f);
                                      wmma::fill_fragment(accL[i][j], 0.0f); }

    auto load_stage = [&](int st, int kb) {
        const __half* bah = (kb < E_) ? (g_ah + ((size_t)kb*T_ + m0)*H_) : (g_hh + (size_t)m0*H_);
        const __half* bal = (kb < E_) ? (g_al + ((size_t)kb*T_ + m0)*H_) : (g_hl + (size_t)m0*H_);
        const __half* bbh = g_Bh + (size_t)kb*64*K3H + n0;
        const __half* bbl = g_Bl + (size_t)kb*64*K3H + n0;
        #pragma unroll
        for (int t = 0; t < 4; t++) {
            int r = lr + 16*t;
            cp16(&Ah[(st*64 + r)*LDA + lc], bah + r*H_ + lc);
            cp16(&Al[(st*64 + r)*LDA + lc], bal + r*H_ + lc);
            cp16(&Bh[(st*64 + r)*LDB + lc], bbh + r*K3H + lc);
            cp16(&Bl[(st*64 + r)*LDB + lc], bbl + r*K3H + lc);
        }
        cp_commit();
    };

    load_stage(0, 0);
    int st = 0;
    for (int kb = 0; kb < 13; kb++) {
        if (kb + 1 < 13) {
            load_stage(st ^ 1, kb + 1);
            asm volatile("cp.async.wait_group 1;\n");
        } else {
            asm volatile("cp.async.wait_group 0;\n");
        }
        __syncthreads();

        const __half* As_ = &Ah[st*64*LDA];
        const __half* Al_ = &Al[st*64*LDA];
        const __half* Bs_ = &Bh[st*64*LDB];
        const __half* Bl_ = &Bl[st*64*LDB];
        #pragma unroll
        for (int kk = 0; kk < 64; kk += 16) {
            wmma::fragment<wmma::matrix_a, 16,16,16, __half, wmma::row_major> afh[2], afl[2];
            wmma::fragment<wmma::matrix_b, 16,16,16, __half, wmma::row_major> bfh[2], bfl[2];
            #pragma unroll
            for (int i = 0; i < 2; i++) {
                wmma::load_matrix_sync(afh[i], As_ + (wm + 16*i)*LDA + kk, LDA);
                wmma::load_matrix_sync(afl[i], Al_ + (wm + 16*i)*LDA + kk, LDA);
            }
            #pragma unroll
            for (int j = 0; j < 2; j++) {
                wmma::load_matrix_sync(bfh[j], Bs_ + kk*LDB + wn + 16*j, LDB);
                wmma::load_matrix_sync(bfl[j], Bl_ + kk*LDB + wn + 16*j, LDB);
            }
            #pragma unroll
            for (int i = 0; i < 2; i++)
                #pragma unroll
                for (int j = 0; j < 2; j++) {
                    wmma::mma_sync(accM[i][j], afh[i], bfh[j], accM[i][j]);
                    wmma::mma_sync(accM[i][j], afh[i], bfl[j], accM[i][j]);
                    wmma::mma_sync(accL[i][j], afl[i], bfh[j], accL[i][j]);
                }
        }
        __syncthreads();
        st ^= 1;
    }

    #pragma unroll
    for (int i = 0; i < 2; i++)
        #pragma unroll
        for (int j = 0; j < 2; j++) {
            #pragma unroll
            for (int k = 0; k < accM[i][j].num_elements; k++)
                accM[i][j].x[k] += accL[i][j].x[k];
            wmma::store_matrix_sync(g_awzrh + (size_t)(m0 + wm + 16*i)*K3H + n0 + wn + 16*j,
                                    accM[i][j], K3H, wmma::mem_row_major);
        }
}

// ---------------------------------------------------------------------------
// K3: gates + h_tilde + blend (fp32), emit fp32 h and hi/lo fp16 planes.
// ---------------------------------------------------------------------------
__global__ __launch_bounds__(256) void k3_update(int it, const float* __restrict__ hidden0,
                                                 float* __restrict__ dout,
                                                 const float* __restrict__ uh) {
    __shared__ float uh_s[64][65];
    __shared__ float rh_s[16][65];

    const int m0  = blockIdx.x * 16;
    const int tid = threadIdx.x;
    const float* h_in  = (it == 0) ? hidden0 : g_hbuf[(it - 1) & 1];
    float*       h_out = (it == ITERS - 1) ? dout : g_hbuf[it & 1];

    for (int i = tid; i < 64*64; i += 256) uh_s[i >> 6][i & 63] = uh[i];
    for (int i = tid; i < 16*64; i += 256) {
        int t = i >> 6, j = i & 63;
        int gt = m0 + t;
        float awr = g_awzrh[gt*K3H + H_ + j] + g_iw[gt*K3H + H_ + j];
        float r = 1.0f / (1.0f + expf(-awr));
        rh_s[t][j] = r * h_in[gt*H_ + j];
    }
    __syncthreads();

    const int t  = tid >> 4;
    const int nb = (tid & 15) << 2;
    const int gt = m0 + t;

    float acc[4];
    #pragma unroll
    for (int q = 0; q < 4; q++) {
        int n = nb + q;
        acc[q] = g_awzrh[gt*K3H + 2*H_ + n] + g_iw[gt*K3H + 2*H_ + n];
    }
    #pragma unroll 4
    for (int j = 0; j < 64; j++) {
        float rv = rh_s[t][j];
        #pragma unroll
        for (int q = 0; q < 4; q++) acc[q] += rv * uh_s[j][nb + q];
    }
    #pragma unroll
    for (int q = 0; q < 4; q++) {
        int n = nb + q;
        float awz = g_awzrh[gt*K3H + n] + g_iw[gt*K3H + n];
        float z  = 1.0f / (1.0f + expf(-awz));
        float hv = h_in[gt*H_ + n];
        float ht = tanhf(acc[q]);
        float o  = (1.0f - z) * hv + z * ht;
        h_out[gt*H_ + n] = o;
        __half hi = __float2half_rn(o);
        g_hh[gt*H_ + n] = hi;
        g_hl[gt*H_ + n] = __float2half_rn(o - __half2float(hi));
    }
}

// ---------------------------------------------------------------------------
extern "C" void kernel_launch(void* const* d_in, const int* in_sizes, int n_in,
                              void* d_out, int out_size) {
    (void)in_sizes; (void)n_in; (void)out_size;
    const float* x      = (const float*)d_in[0];
    const float* hidden = (const float*)d_in[1];
    const float* edge   = (const float*)d_in[2];
    const float* ba     = (const float*)d_in[3];
    const float* w      = (const float*)d_in[4];
    const float* uzr    = (const float*)d_in[5];
    const float* uh     = (const float*)d_in[6];
    const float* wi     = (const float*)d_in[7];
    const float* bw     = (const float*)d_in[8];
    float* out = (float*)d_out;

    cudaFuncSetAttribute(k1_act,   cudaFuncAttributeMaxDynamicSharedMemorySize, SMEM_K1);
    cudaFuncSetAttribute(k2_awzrh, cudaFuncAttributeMaxDynamicSharedMemorySize, SMEM_K1);

    p1_conv_edge<<< (int)(((size_t)E_*T_*T_/4) / 256), 256 >>>(edge);
    p2_build_b <<< (KTOT*K3H + 255) / 256, 256 >>>(w, uzr);
    p4_h16     <<< (T_*H_) / 256, 256 >>>(hidden);
    p3_iw      <<< T_, K3H >>>(x, wi, bw);

    for (int it = 0; it < ITERS; ++it) {
        k1_act   <<< dim3(T_/64, E_), 128, SMEM_K1 >>>(ba);
        k2_awzrh <<< dim3(T_/64, 3),  128, SMEM_K1 >>>();
        k3_update<<< T_/16,           256 >>>(it, hidden, out, uh);
    }
}

// round 5
// speedup vs baseline: 1.4092x; 1.4092x over previous
#include <cuda_runtime.h>
#include <cuda_fp16.h>
#include <mma.h>
#include <cstdint>

using namespace nvcuda;

constexpr int E_   = 12;
constexpr int T_   = 2048;
constexpr int H_   = 64;
constexpr int IN_  = 128;
constexpr int K3H  = 192;
constexpr int ITERS = 10;
constexpr int KTOT = E_*H_ + H_;    // 832

// ---------------------------------------------------------------------------
// Device scratch
// ---------------------------------------------------------------------------
__device__ __half g_eh[(size_t)E_*T_*T_];   // edge hi  [e][s][t]
__device__ __half g_el[(size_t)E_*T_*T_];   // edge lo  [e][s][t]
__device__ __half g_hh[T_*H_],  g_hl[T_*H_];    // hidden hi/lo  [s][h]
__device__ float  g_actf[(size_t)E_*T_*H_];     // fp32 act accumulators
__device__ __half g_ah[(size_t)E_*T_*H_];   // act hi [e][t][h]
__device__ __half g_al[(size_t)E_*T_*H_];   // act lo
__device__ __half g_Bh[KTOT*K3H], g_Bl[KTOT*K3H];
__device__ float  g_iw[T_*K3H];
__device__ float  g_awzrh[T_*K3H];
__device__ float  g_hbuf[2][T_*H_];

// ---------------------------------------------------------------------------
// Helpers
// ---------------------------------------------------------------------------
__device__ __forceinline__ void cp16(void* s, const void* g) {
    unsigned sa = (unsigned)__cvta_generic_to_shared(s);
    asm volatile("cp.async.ca.shared.global [%0], [%1], 16;\n" :: "r"(sa), "l"(g));
}
__device__ __forceinline__ void cp_commit() { asm volatile("cp.async.commit_group;\n"); }

// ---------------------------------------------------------------------------
// Pre-pass
// ---------------------------------------------------------------------------
__global__ void p1_conv_edge(const float* __restrict__ e) {
    size_t i = (size_t)blockIdx.x * blockDim.x + threadIdx.x;   // one float4 each
    float4 v = reinterpret_cast<const float4*>(e)[i];
    __half hx = __float2half_rn(v.x), hy = __float2half_rn(v.y);
    __half hz = __float2half_rn(v.z), hw = __float2half_rn(v.w);
    __half2* dh = reinterpret_cast<__half2*>(g_eh);
    __half2* dl = reinterpret_cast<__half2*>(g_el);
    dh[2*i]   = __halves2half2(hx, hy);
    dh[2*i+1] = __halves2half2(hz, hw);
    dl[2*i]   = __floats2half2_rn(v.x - __half2float(hx), v.y - __half2float(hy));
    dl[2*i+1] = __floats2half2_rn(v.z - __half2float(hz), v.w - __half2float(hw));
}

__global__ void p2_build_b(const float* __restrict__ w, const float* __restrict__ uzr) {
    int i = blockIdx.x * blockDim.x + threadIdx.x;
    if (i >= KTOT * K3H) return;
    int k = i / K3H, n = i % K3H;
    float v;
    if (k < E_*H_) v = w[i];
    else { int j = k - E_*H_; v = (n < 2*H_) ? uzr[j*2*H_ + n] : 0.0f; }
    __half hi = __float2half_rn(v);
    g_Bh[i] = hi;
    g_Bl[i] = __float2half_rn(v - __half2float(hi));
}

__global__ void p4_h16(const float* __restrict__ h) {
    int i = blockIdx.x * blockDim.x + threadIdx.x;
    float v = h[i];
    __half hi = __float2half_rn(v);
    g_hh[i] = hi;
    g_hl[i] = __float2half_rn(v - __half2float(hi));
}

__global__ void p3_iw(const float* __restrict__ x, const float* __restrict__ wi,
                      const float* __restrict__ bw) {
    __shared__ float xs[IN_];
    int t = blockIdx.x;
    if (threadIdx.x < IN_) xs[threadIdx.x] = x[t*IN_ + threadIdx.x];
    __syncthreads();
    int n = threadIdx.x;
    float acc = bw[n];
    #pragma unroll 8
    for (int k = 0; k < IN_; k++) acc += xs[k] * wi[k*K3H + n];
    g_iw[t*K3H + n] = acc;
}

// ---------------------------------------------------------------------------
// z0: zero fp32 act accumulators (needed each iteration before K1's red.add)
// ---------------------------------------------------------------------------
__global__ void z0_zero_act() {
    size_t i = (size_t)blockIdx.x * blockDim.x + threadIdx.x;
    reinterpret_cast<float4*>(g_actf)[i] = make_float4(0.f, 0.f, 0.f, 0.f);
}

// ---------------------------------------------------------------------------
// K1: partial act (split-K=2): C += edge^T @ h (3-term hi/lo), red.add to g_actf
// CTA tile 128m x 64n, 4 warps (warp tile 64x32), 2-stage cp.async (k=32).
// A col-major in smem as [k][m], B row-major [k][n].
// ---------------------------------------------------------------------------
constexpr int K1_LDA = 136;                   // 128 + 8 pad (halves)
constexpr int K1_LDB = 72;                    // 64 + 8 pad
constexpr int K1_APL = 32 * K1_LDA;           // halves per A plane per stage
constexpr int K1_BPL = 32 * K1_LDB;
constexpr int K1_STAGE = 2*K1_APL + 2*K1_BPL; // halves per stage
constexpr int K1_SMEM = 2 * K1_STAGE * 2;     // bytes = 53248
constexpr int K1_LDC = 68;

__global__ __launch_bounds__(128, 3) void k1_act() {
    extern __shared__ __half sm[];

    const int e      = blockIdx.y;
    const int m0     = blockIdx.x * 128;
    const int k_base = blockIdx.z * 1024;     // split-K half

    const int tid  = threadIdx.x;
    const int warp = tid >> 5;
    const int wm = (warp & 1) * 64;           // 2 warps along m
    const int wn = (warp >> 1) * 32;          // 2 warps along n

    const __half* Agh = g_eh + (size_t)e * T_ * T_;
    const __half* Agl = g_el + (size_t)e * T_ * T_;

    wmma::fragment<wmma::accumulator, 16,16,16, float> acc[4][2];
    #pragma unroll
    for (int i = 0; i < 4; i++)
        #pragma unroll
        for (int j = 0; j < 2; j++) wmma::fill_fragment(acc[i][j], 0.0f);

    auto load_stage = [&](int kb) {
        __half* base = sm + (kb & 1) * K1_STAGE;
        __half* Ah = base;
        __half* Al = base + K1_APL;
        __half* Bh = base + 2*K1_APL;
        __half* Bl = base + 2*K1_APL + K1_BPL;
        const int k0 = k_base + kb * 32;
        #pragma unroll
        for (int i = 0; i < 4; i++) {             // A: 512 chunks/plane
            int c = tid + i * 128;
            int r = c >> 4, mc = (c & 15) * 8;
            const size_t go = (size_t)(k0 + r) * T_ + m0 + mc;
            cp16(Ah + r*K1_LDA + mc, Agh + go);
            cp16(Al + r*K1_LDA + mc, Agl + go);
        }
        #pragma unroll
        for (int i = 0; i < 2; i++) {             // B: 256 chunks/plane
            int c = tid + i * 128;
            int r = c >> 3, nc = (c & 7) * 8;
            const size_t go = (size_t)(k0 + r) * H_ + nc;
            cp16(Bh + r*K1_LDB + nc, g_hh + go);
            cp16(Bl + r*K1_LDB + nc, g_hl + go);
        }
        cp_commit();
    };

    load_stage(0);
    for (int kb = 0; kb < 32; kb++) {
        asm volatile("cp.async.wait_group 0;\n" ::: "memory");
        __syncthreads();
        if (kb < 31) load_stage(kb + 1);          // overlaps compute below

        const __half* base = sm + (kb & 1) * K1_STAGE;
        const __half* Ah = base;
        const __half* Al = base + K1_APL;
        const __half* Bh = base + 2*K1_APL;
        const __half* Bl = base + 2*K1_APL + K1_BPL;

        #pragma unroll
        for (int kk = 0; kk < 32; kk += 16) {
            wmma::fragment<wmma::matrix_b, 16,16,16, __half, wmma::row_major> bfh[2], bfl[2];
            #pragma unroll
            for (int j = 0; j < 2; j++) {
                wmma::load_matrix_sync(bfh[j], Bh + kk*K1_LDB + wn + 16*j, K1_LDB);
                wmma::load_matrix_sync(bfl[j], Bl + kk*K1_LDB + wn + 16*j, K1_LDB);
            }
            #pragma unroll
            for (int i = 0; i < 4; i++) {
                wmma::fragment<wmma::matrix_a, 16,16,16, __half, wmma::col_major> afh, afl;
                wmma::load_matrix_sync(afh, Ah + kk*K1_LDA + wm + 16*i, K1_LDA);
                wmma::load_matrix_sync(afl, Al + kk*K1_LDA + wm + 16*i, K1_LDA);
                #pragma unroll
                for (int j = 0; j < 2; j++) {
                    wmma::mma_sync(acc[i][j], afh, bfh[j], acc[i][j]);
                    wmma::mma_sync(acc[i][j], afh, bfl[j], acc[i][j]);
                    wmma::mma_sync(acc[i][j], afl, bfh[j], acc[i][j]);
                }
            }
        }
        __syncthreads();
    }

    // Epilogue: frags -> smem -> red.add into fp32 accumulator
    float* Cs = reinterpret_cast<float*>(sm);
    #pragma unroll
    for (int i = 0; i < 4; i++)
        #pragma unroll
        for (int j = 0; j < 2; j++)
            wmma::store_matrix_sync(Cs + (wm + 16*i)*K1_LDC + wn + 16*j, acc[i][j],
                                    K1_LDC, wmma::mem_row_major);
    __syncthreads();
    float* dst = g_actf + ((size_t)e * T_ + m0) * H_;
    for (int idx = tid; idx < 128*64; idx += 128) {
        int r = idx >> 6, c = idx & 63;
        atomicAdd(dst + (size_t)r * H_ + c, Cs[r*K1_LDC + c]);
    }
}

// ---------------------------------------------------------------------------
// kconv: act fp32 + ba  ->  hi/lo fp16 planes for K2
// ---------------------------------------------------------------------------
__global__ void kconv(const float* __restrict__ ba) {
    size_t gid = (size_t)blockIdx.x * blockDim.x + threadIdx.x;   // one float4
    float4 v = reinterpret_cast<const float4*>(g_actf)[gid];
    size_t i4 = gid * 4;
    int e  = (int)(i4 / (T_ * H_));
    int c0 = (int)(i4 & 63);
    v.x += ba[e*H_ + c0];     v.y += ba[e*H_ + c0 + 1];
    v.z += ba[e*H_ + c0 + 2]; v.w += ba[e*H_ + c0 + 3];
    __half2 h0 = __floats2half2_rn(v.x, v.y);
    __half2 h1 = __floats2half2_rn(v.z, v.w);
    __half2 l0 = __floats2half2_rn(v.x - __low2float(h0), v.y - __high2float(h0));
    __half2 l1 = __floats2half2_rn(v.z - __low2float(h1), v.w - __high2float(h1));
    reinterpret_cast<__half2*>(g_ah)[gid*2]   = h0;
    reinterpret_cast<__half2*>(g_ah)[gid*2+1] = h1;
    reinterpret_cast<__half2*>(g_al)[gid*2]   = l0;
    reinterpret_cast<__half2*>(g_al)[gid*2+1] = l1;
}

// ---------------------------------------------------------------------------
// K2: awzrh = [act | h] @ [W ; uz_ur|0]  (M=2048, K=832, N=192), WMMA 3-term.
// (identical to the R3 passing version)
// ---------------------------------------------------------------------------
constexpr int LDA = 72, LDB = 72;
constexpr int STG = 64 * LDA;
constexpr int SMEM_K2 = 4 * 2 * STG * 2;

__global__ __launch_bounds__(128) void k2_awzrh() {
    extern __shared__ __half smem[];
    __half* Ah = smem;
    __half* Al = smem + 2*STG;
    __half* Bh = smem + 4*STG;
    __half* Bl = smem + 6*STG;

    const int m0 = blockIdx.x * 64;
    const int n0 = blockIdx.y * 64;
    const int tid  = threadIdx.x;
    const int warp = tid >> 5;
    const int wm = (warp & 1) * 32, wn = (warp >> 1) * 32;
    const int lr = tid >> 3;
    const int lc = (tid & 7) * 8;

    wmma::fragment<wmma::accumulator, 16,16,16, float> accM[2][2], accL[2][2];
    #pragma unroll
    for (int i = 0; i < 2; i++)
        #pragma unroll
        for (int j = 0; j < 2; j++) { wmma::fill_fragment(accM[i][j], 0.0f);
                                      wmma::fill_fragment(accL[i][j], 0.0f); }

    auto load_stage = [&](int st, int kb) {
        const __half* bah = (kb < E_) ? (g_ah + ((size_t)kb*T_ + m0)*H_) : (g_hh + (size_t)m0*H_);
        const __half* bal = (kb < E_) ? (g_al + ((size_t)kb*T_ + m0)*H_) : (g_hl + (size_t)m0*H_);
        const __half* bbh = g_Bh + (size_t)kb*64*K3H + n0;
        const __half* bbl = g_Bl + (size_t)kb*64*K3H + n0;
        #pragma unroll
        for (int t = 0; t < 4; t++) {
            int r = lr + 16*t;
            cp16(&Ah[(st*64 + r)*LDA + lc], bah + r*H_ + lc);
            cp16(&Al[(st*64 + r)*LDA + lc], bal + r*H_ + lc);
            cp16(&Bh[(st*64 + r)*LDB + lc], bbh + r*K3H + lc);
            cp16(&Bl[(st*64 + r)*LDB + lc], bbl + r*K3H + lc);
        }
        cp_commit();
    };

    load_stage(0, 0);
    int st = 0;
    for (int kb = 0; kb < 13; kb++) {
        if (kb + 1 < 13) {
            load_stage(st ^ 1, kb + 1);
            asm volatile("cp.async.wait_group 1;\n");
        } else {
            asm volatile("cp.async.wait_group 0;\n");
        }
        __syncthreads();

        const __half* As_ = &Ah[st*64*LDA];
        const __half* Al_ = &Al[st*64*LDA];
        const __half* Bs_ = &Bh[st*64*LDB];
        const __half* Bl_ = &Bl[st*64*LDB];
        #pragma unroll
        for (int kk = 0; kk < 64; kk += 16) {
            wmma::fragment<wmma::matrix_a, 16,16,16, __half, wmma::row_major> afh[2], afl[2];
            wmma::fragment<wmma::matrix_b, 16,16,16, __half, wmma::row_major> bfh[2], bfl[2];
            #pragma unroll
            for (int i = 0; i < 2; i++) {
                wmma::load_matrix_sync(afh[i], As_ + (wm + 16*i)*LDA + kk, LDA);
                wmma::load_matrix_sync(afl[i], Al_ + (wm + 16*i)*LDA + kk, LDA);
            }
            #pragma unroll
            for (int j = 0; j < 2; j++) {
                wmma::load_matrix_sync(bfh[j], Bs_ + kk*LDB + wn + 16*j, LDB);
                wmma::load_matrix_sync(bfl[j], Bl_ + kk*LDB + wn + 16*j, LDB);
            }
            #pragma unroll
            for (int i = 0; i < 2; i++)
                #pragma unroll
                for (int j = 0; j < 2; j++) {
                    wmma::mma_sync(accM[i][j], afh[i], bfh[j], accM[i][j]);
                    wmma::mma_sync(accM[i][j], afh[i], bfl[j], accM[i][j]);
                    wmma::mma_sync(accL[i][j], afl[i], bfh[j], accL[i][j]);
                }
        }
        __syncthreads();
        st ^= 1;
    }

    #pragma unroll
    for (int i = 0; i < 2; i++)
        #pragma unroll
        for (int j = 0; j < 2; j++) {
            #pragma unroll
            for (int k = 0; k < accM[i][j].num_elements; k++)
                accM[i][j].x[k] += accL[i][j].x[k];
            wmma::store_matrix_sync(g_awzrh + (size_t)(m0 + wm + 16*i)*K3H + n0 + wn + 16*j,
                                    accM[i][j], K3H, wmma::mem_row_major);
        }
}

// ---------------------------------------------------------------------------
// K3: gates + h_tilde + blend (fp32), emit fp32 h and hi/lo fp16 planes.
// ---------------------------------------------------------------------------
__global__ __launch_bounds__(256) void k3_update(int it, const float* __restrict__ hidden0,
                                                 float* __restrict__ dout,
                                                 const float* __restrict__ uh) {
    __shared__ float uh_s[64][65];
    __shared__ float rh_s[16][65];

    const int m0  = blockIdx.x * 16;
    const int tid = threadIdx.x;
    const float* h_in  = (it == 0) ? hidden0 : g_hbuf[(it - 1) & 1];
    float*       h_out = (it == ITERS - 1) ? dout : g_hbuf[it & 1];

    for (int i = tid; i < 64*64; i += 256) uh_s[i >> 6][i & 63] = uh[i];
    for (int i = tid; i < 16*64; i += 256) {
        int t = i >> 6, j = i & 63;
        int gt = m0 + t;
        float awr = g_awzrh[gt*K3H + H_ + j] + g_iw[gt*K3H + H_ + j];
        float r = 1.0f / (1.0f + expf(-awr));
        rh_s[t][j] = r * h_in[gt*H_ + j];
    }
    __syncthreads();

    const int t  = tid >> 4;
    const int nb = (tid & 15) << 2;
    const int gt = m0 + t;

    float acc[4];
    #pragma unroll
    for (int q = 0; q < 4; q++) {
        int n = nb + q;
        acc[q] = g_awzrh[gt*K3H + 2*H_ + n] + g_iw[gt*K3H + 2*H_ + n];
    }
    #pragma unroll 4
    for (int j = 0; j < 64; j++) {
        float rv = rh_s[t][j];
        #pragma unroll
        for (int q = 0; q < 4; q++) acc[q] += rv * uh_s[j][nb + q];
    }
    #pragma unroll
    for (int q = 0; q < 4; q++) {
        int n = nb + q;
        float awz = g_awzrh[gt*K3H + n] + g_iw[gt*K3H + n];
        float z  = 1.0f / (1.0f + expf(-awz));
        float hv = h_in[gt*H_ + n];
        float ht = tanhf(acc[q]);
        float o  = (1.0f - z) * hv + z * ht;
        h_out[gt*H_ + n] = o;
        __half hi = __float2half_rn(o);
        g_hh[gt*H_ + n] = hi;
        g_hl[gt*H_ + n] = __float2half_rn(o - __half2float(hi));
    }
}

// ---------------------------------------------------------------------------
extern "C" void kernel_launch(void* const* d_in, const int* in_sizes, int n_in,
                              void* d_out, int out_size) {
    (void)in_sizes; (void)n_in; (void)out_size;
    const float* x      = (const float*)d_in[0];
    const float* hidden = (const float*)d_in[1];
    const float* edge   = (const float*)d_in[2];
    const float* ba     = (const float*)d_in[3];
    const float* w      = (const float*)d_in[4];
    const float* uzr    = (const float*)d_in[5];
    const float* uh     = (const float*)d_in[6];
    const float* wi     = (const float*)d_in[7];
    const float* bw     = (const float*)d_in[8];
    float* out = (float*)d_out;

    cudaFuncSetAttribute(k1_act,   cudaFuncAttributeMaxDynamicSharedMemorySize, K1_SMEM);
    cudaFuncSetAttribute(k2_awzrh, cudaFuncAttributeMaxDynamicSharedMemorySize, SMEM_K2);

    p1_conv_edge<<< (int)(((size_t)E_*T_*T_/4) / 256), 256 >>>(edge);
    p2_build_b  <<< (KTOT*K3H + 255) / 256, 256 >>>(w, uzr);
    p4_h16      <<< (T_*H_) / 256, 256 >>>(hidden);
    p3_iw       <<< T_, K3H >>>(x, wi, bw);

    constexpr int ACT4 = E_*T_*H_ / 4;   // float4 count
    for (int it = 0; it < ITERS; ++it) {
        z0_zero_act<<< ACT4 / 256, 256 >>>();
        k1_act   <<< dim3(T_/128, E_, 2), 128, K1_SMEM >>>();
        kconv    <<< ACT4 / 256, 256 >>>(ba);
        k2_awzrh <<< dim3(T_/64, 3),   128, SMEM_K2 >>>();
        k3_update<<< T_/16,            256 >>>(it, hidden, out, uh);
    }
}